// round 2
// baseline (speedup 1.0000x reference)
#include <cuda_runtime.h>
#include <cuda_bf16.h>
#include <math.h>

// ---------------- problem constants ----------------
#define TOK    6272      // B*H*W tokens
#define BSZ    2
#define HH     56
#define WWW    56
#define LSEQ   3136      // H*W
#define DM     96        // d_model
#define DI     192       // d_inner
#define N2     384       // 2*d_inner
#define NST    16        // d_state
#define RK     6         // dt_rank
#define GSEQ   8         // 4 dirs * B
#define NCH    56        // chunks per sequence (one image row each)
#define CLEN   56        // chunk length
#define CQ     4         // channel quarters
#define CPQ    48        // channels per quarter

// ---------------- scratch (static device memory; no allocs) ----------------
__device__ float  g_xm[TOK * DI];
__device__ float  g_z [TOK * DI];
__device__ float  g_xc[TOK * DI];
__device__ float  g_dt[TOK * DI];
__device__ float  g_Bv[TOK * NST];
__device__ float  g_Cv[TOK * NST];
__device__ float2 g_ab[GSEQ * NCH * DI * NST];   // (a_prod, h_end) per chunk
__device__ float  g_hs[GSEQ * NCH * DI * NST];   // h_start per chunk
__device__ float  g_ys[GSEQ * LSEQ * DI];        // per-direction scan output

// ---------------- kernel 1: xz = x @ W_in, split into xm / z ----------------
// M=6272, N=384, K=96.  32x128 tile, 256 threads, 4x4 micro-tile, K in 2 chunks of 48.
__global__ void k_inproj(const float* __restrict__ x, const float* __restrict__ Wi) {
    __shared__ float sx[48 * 32];    // [kk][m]
    __shared__ float sw[48 * 128];   // [kk][n]
    const int m0 = blockIdx.x * 32;
    const int n0 = blockIdx.y * 128;
    const int tid = threadIdx.x;
    const int tm = tid >> 5;   // 0..7  -> 4 tokens
    const int tn = tid & 31;   // 0..31 -> 4 cols
    float acc[4][4] = {};
    for (int k0 = 0; k0 < 96; k0 += 48) {
        __syncthreads();
        for (int idx = tid; idx < 32 * 48; idx += 256) {
            int i = idx / 48, kk = idx - i * 48;
            sx[kk * 32 + i] = x[(m0 + i) * 96 + k0 + kk];
        }
        for (int idx = tid; idx < 48 * 128; idx += 256) {
            int kk = idx >> 7, nn = idx & 127;
            sw[kk * 128 + nn] = Wi[(k0 + kk) * 384 + n0 + nn];
        }
        __syncthreads();
#pragma unroll 16
        for (int kk = 0; kk < 48; kk++) {
            float4 a  = *(const float4*)&sx[kk * 32  + tm * 4];
            float4 bv = *(const float4*)&sw[kk * 128 + tn * 4];
            acc[0][0] = fmaf(a.x, bv.x, acc[0][0]); acc[0][1] = fmaf(a.x, bv.y, acc[0][1]);
            acc[0][2] = fmaf(a.x, bv.z, acc[0][2]); acc[0][3] = fmaf(a.x, bv.w, acc[0][3]);
            acc[1][0] = fmaf(a.y, bv.x, acc[1][0]); acc[1][1] = fmaf(a.y, bv.y, acc[1][1]);
            acc[1][2] = fmaf(a.y, bv.z, acc[1][2]); acc[1][3] = fmaf(a.y, bv.w, acc[1][3]);
            acc[2][0] = fmaf(a.z, bv.x, acc[2][0]); acc[2][1] = fmaf(a.z, bv.y, acc[2][1]);
            acc[2][2] = fmaf(a.z, bv.z, acc[2][2]); acc[2][3] = fmaf(a.z, bv.w, acc[2][3]);
            acc[3][0] = fmaf(a.w, bv.x, acc[3][0]); acc[3][1] = fmaf(a.w, bv.y, acc[3][1]);
            acc[3][2] = fmaf(a.w, bv.z, acc[3][2]); acc[3][3] = fmaf(a.w, bv.w, acc[3][3]);
        }
    }
#pragma unroll
    for (int i = 0; i < 4; i++) {
        int m = m0 + tm * 4 + i;
#pragma unroll
        for (int j = 0; j < 4; j++) {
            int n = n0 + tn * 4 + j;
            float v = acc[i][j];
            if (n < DI) g_xm[m * DI + n] = v;
            else        g_z [m * DI + (n - DI)] = v;
        }
    }
}

// ---------------- kernel 2: depthwise 3x3 conv + bias ----------------
__global__ void k_conv(const float* __restrict__ cw, const float* __restrict__ cb) {
    int idx = blockIdx.x * 256 + threadIdx.x;
    if (idx >= TOK * DI) return;
    int c = idx % DI, t = idx / DI;
    int b = t / LSEQ, r = t - b * LSEQ, h = r / WWW, w = r - h * WWW;
    float acc = cb[c];
#pragma unroll
    for (int dh = -1; dh <= 1; dh++) {
#pragma unroll
        for (int dw = -1; dw <= 1; dw++) {
            int hh = h + dh, ww = w + dw;
            if ((unsigned)hh < HH && (unsigned)ww < WWW)
                acc = fmaf(g_xm[(b * LSEQ + hh * WWW + ww) * DI + c],
                           cw[((dh + 1) * 3 + (dw + 1)) * DI + c], acc);
        }
    }
    g_xc[idx] = acc;
}

// ---------------- kernel 3: x-proj (dtr,B,C) + dt-proj + softplus ----------------
__global__ void k_xproj(const float* __restrict__ Wx, const float* __restrict__ Wd,
                        const float* __restrict__ bd) {
    const int t = blockIdx.x;
    __shared__ float sx[DI];
    __shared__ float spr[RK];
    const int tid = threadIdx.x;  // 192
    sx[tid] = g_xc[t * DI + tid];
    __syncthreads();
    if (tid < RK + 2 * NST) {
        float a = 0.f;
#pragma unroll 8
        for (int k = 0; k < DI; k++) a = fmaf(sx[k], Wx[k * (RK + 2 * NST) + tid], a);
        if (tid < RK)            spr[tid] = a;
        else if (tid < RK + NST) g_Bv[t * NST + tid - RK] = a;
        else                     g_Cv[t * NST + tid - RK - NST] = a;
    }
    __syncthreads();
    float a = bd[tid];
#pragma unroll
    for (int r = 0; r < RK; r++) a = fmaf(spr[r], Wd[r * DI + tid], a);
    g_dt[t * DI + tid] = (a > 20.f) ? a : log1pf(expf(a));
}

// direction mapping: chunk ch = row index i, l = pos in row j
__device__ __forceinline__ int map_token(int d, int b, int i, int j) {
    int h, w;
    if      (d == 0) { h = i; w = j;        }
    else if (d == 1) { h = i; w = 55 - j;   }
    else if (d == 2) { h = j; w = i;        }
    else             { h = j; w = 55 - i;   }
    return b * LSEQ + h * WWW + w;
}

// ---------------- kernel 4: scan pass 1 (per-chunk a_prod, h_end) ----------------
__global__ void k_scan1(const float* __restrict__ A_log) {
    const int bx = blockIdx.x;          // 1792 = 8*56*4
    const int cq = bx & 3;
    const int ch = (bx >> 2) % NCH;
    const int g  = bx / (NCH * CQ);
    const int d  = g >> 1, b = g & 1;
    __shared__ float s_dt[CLEN * CPQ], s_x[CLEN * CPQ], s_B[CLEN * NST];
    const int tid = threadIdx.x;        // 768
    for (int idx = tid; idx < CLEN * 112; idx += 768) {
        int l = idx / 112, r = idx - l * 112;
        int t = map_token(d, b, ch, l);
        if (r < 48)      s_dt[l * 48 + r]      = g_dt[t * DI + cq * 48 + r];
        else if (r < 96) s_x [l * 48 + r - 48] = g_xc[t * DI + cq * 48 + r - 48];
        else             s_B [l * 16 + r - 96] = g_Bv[t * NST + r - 96];
    }
    __syncthreads();
    const int n = tid & 15, cl = tid >> 4;
    const int c = cq * 48 + cl;
    const float acoef = -__expf(A_log[c * NST + n]);
    float h = 0.f, ap = 1.f;
#pragma unroll 8
    for (int l = 0; l < CLEN; l++) {
        float dt = s_dt[l * 48 + cl];
        float a  = __expf(acoef * dt);
        float bv = dt * s_B[l * 16 + n] * s_x[l * 48 + cl];
        h  = fmaf(a, h, bv);
        ap *= a;
    }
    g_ab[((g * NCH + ch) * DI + c) * NST + n] = make_float2(ap, h);
}

// ---------------- kernel 5: cross-chunk prefix combine ----------------
__global__ void k_combine() {
    int s = blockIdx.x * 256 + threadIdx.x;   // 24576 states
    if (s >= GSEQ * DI * NST) return;
    int g = s / (DI * NST), sc = s - g * (DI * NST);
    float h = 0.f;
#pragma unroll 8
    for (int k = 0; k < NCH; k++) {
        int idx = (g * NCH + k) * (DI * NST) + sc;
        float2 ab = g_ab[idx];
        g_hs[idx] = h;
        h = fmaf(ab.x, h, ab.y);
    }
}

// ---------------- kernel 6: scan pass 2 (replay + emit y) ----------------
__global__ void k_scan2(const float* __restrict__ A_log, const float* __restrict__ D_skip) {
    const int bx = blockIdx.x;
    const int cq = bx & 3;
    const int ch = (bx >> 2) % NCH;
    const int g  = bx / (NCH * CQ);
    const int d  = g >> 1, b = g & 1;
    __shared__ float s_dt[CLEN * CPQ], s_x[CLEN * CPQ], s_B[CLEN * NST], s_C[CLEN * NST];
    const int tid = threadIdx.x;        // 768
    for (int idx = tid; idx < CLEN * 128; idx += 768) {
        int l = idx >> 7, r = idx & 127;
        int t = map_token(d, b, ch, l);
        if (r < 48)       s_dt[l * 48 + r]       = g_dt[t * DI + cq * 48 + r];
        else if (r < 96)  s_x [l * 48 + r - 48]  = g_xc[t * DI + cq * 48 + r - 48];
        else if (r < 112) s_B [l * 16 + r - 96]  = g_Bv[t * NST + r - 96];
        else              s_C [l * 16 + r - 112] = g_Cv[t * NST + r - 112];
    }
    __syncthreads();
    const int n = tid & 15, cl = tid >> 4;
    const int c = cq * 48 + cl;
    const float acoef = -__expf(A_log[c * NST + n]);
    const float dsk = D_skip[c];
    float h = g_hs[((g * NCH + ch) * DI + c) * NST + n];
#pragma unroll 4
    for (int l = 0; l < CLEN; l++) {
        float dt = s_dt[l * 48 + cl];
        float a  = __expf(acoef * dt);
        float xv = s_x[l * 48 + cl];
        float bv = dt * s_B[l * 16 + n] * xv;
        h = fmaf(a, h, bv);
        float p = h * s_C[l * 16 + n];
        p += __shfl_xor_sync(0xffffffffu, p, 8);
        p += __shfl_xor_sync(0xffffffffu, p, 4);
        p += __shfl_xor_sync(0xffffffffu, p, 2);
        p += __shfl_xor_sync(0xffffffffu, p, 1);
        if (n == 0)
            g_ys[(g * LSEQ + ch * CLEN + l) * DI + c] = fmaf(dsk, xv, p);
    }
}

// ---------------- kernel 7: sum dirs, silu gate, out-proj ----------------
__global__ void k_final(const float* __restrict__ Wo, float* __restrict__ out) {
    const int t0 = blockIdx.x * 32;
    __shared__ float sy[32 * DI];   // 24 KB
    const int tid = threadIdx.x;    // 256
    for (int idx = tid; idx < 32 * DI; idx += 256) {
        int i = idx / DI, c = idx - i * DI;
        int t = t0 + i;
        int b = t / LSEQ, l = t - b * LSEQ;
        float ys = 0.f;
#pragma unroll
        for (int dd = 0; dd < 4; dd++)
            ys += g_ys[((dd * 2 + b) * LSEQ + l) * DI + c];
        float z = g_z[t * DI + c];
        float act = z / (1.f + __expf(-z));
        sy[i * DI + c] = act * ys;
    }
    __syncthreads();
    const int tm = tid >> 5;   // 0..7 -> 4 tokens
    const int tn = tid & 31;   // 0..31 -> 3 outputs (stride 32)
    float acc[4][3] = {};
#pragma unroll 8
    for (int k = 0; k < DI; k++) {
        float w0 = Wo[k * DM + tn];
        float w1 = Wo[k * DM + 32 + tn];
        float w2 = Wo[k * DM + 64 + tn];
#pragma unroll
        for (int i = 0; i < 4; i++) {
            float a = sy[(tm * 4 + i) * DI + k];
            acc[i][0] = fmaf(a, w0, acc[i][0]);
            acc[i][1] = fmaf(a, w1, acc[i][1]);
            acc[i][2] = fmaf(a, w2, acc[i][2]);
        }
    }
#pragma unroll
    for (int i = 0; i < 4; i++) {
        int t = t0 + tm * 4 + i;
        out[t * DM + tn]      = acc[i][0];
        out[t * DM + 32 + tn] = acc[i][1];
        out[t * DM + 64 + tn] = acc[i][2];
    }
}

// ---------------- launcher ----------------
extern "C" void kernel_launch(void* const* d_in, const int* in_sizes, int n_in,
                              void* d_out, int out_size) {
    const float* x      = (const float*)d_in[0];
    const float* W_in   = (const float*)d_in[1];
    const float* conv_w = (const float*)d_in[2];
    const float* conv_b = (const float*)d_in[3];
    const float* W_xpr  = (const float*)d_in[4];
    const float* W_dt   = (const float*)d_in[5];
    const float* b_dt   = (const float*)d_in[6];
    const float* A_log  = (const float*)d_in[7];
    const float* D_skip = (const float*)d_in[8];
    const float* W_out  = (const float*)d_in[9];
    float* out = (float*)d_out;

    dim3 g1(TOK / 32, N2 / 128);
    k_inproj<<<g1, 256>>>(x, W_in);
    k_conv<<<(TOK * DI + 255) / 256, 256>>>(conv_w, conv_b);
    k_xproj<<<TOK, DI>>>(W_xpr, W_dt, b_dt);
    k_scan1<<<GSEQ * NCH * CQ, 768>>>(A_log);
    k_combine<<<(GSEQ * DI * NST + 255) / 256, 256>>>();
    k_scan2<<<GSEQ * NCH * CQ, 768>>>(A_log, D_skip);
    k_final<<<TOK / 32, 256>>>(W_out, out);
}

// round 3
// speedup vs baseline: 1.4530x; 1.4530x over previous
#include <cuda_runtime.h>
#include <cuda_bf16.h>
#include <math.h>

// ---------------- problem constants ----------------
#define TOK    6272
#define BSZ    2
#define HH     56
#define WWW    56
#define LSEQ   3136
#define DM     96
#define DI     192
#define N2     384
#define NST    16
#define RK     6
#define GSEQ   8
#define NCH    56
#define CLEN   56

// ---------------- scratch ----------------
__device__ float g_xm [TOK * DI];
__device__ float g_z  [TOK * DI];
__device__ float g_xc [TOK * DI];
__device__ float g_dt [TOK * DI];
__device__ float g_dtr[TOK * RK];
__device__ float g_Bv [TOK * NST];
__device__ float g_Cv [TOK * NST];
__device__ float g_ap [GSEQ * NCH * DI * NST];
__device__ float g_he [GSEQ * NCH * DI * NST];
__device__ float g_hs [GSEQ * NCH * DI * NST];
__device__ float g_ys [GSEQ * LSEQ * DI];

__device__ __forceinline__ float ex2(float x) {
    float r; asm("ex2.approx.f32 %0, %1;" : "=f"(r) : "f"(x)); return r;
}

// seq position l in chunk ch maps to token t0 + l*st
__device__ __forceinline__ void seq_base(int d, int b, int ch, int& t0, int& st) {
    if      (d == 0) { t0 = b * LSEQ + ch * WWW;      st = 1;   }
    else if (d == 1) { t0 = b * LSEQ + ch * WWW + 55; st = -1;  }
    else if (d == 2) { t0 = b * LSEQ + ch;            st = WWW; }
    else             { t0 = b * LSEQ + (55 - ch);     st = WWW; }
}

// ---------------- kernel 1: xz = x @ W_in -> xm / z ----------------
// 64x128 tile, 256 thr, 4x8 micro
__global__ void __launch_bounds__(256) k_inproj(const float* __restrict__ x,
                                                const float* __restrict__ Wi) {
    __shared__ float sx[48 * 64];
    __shared__ float sw[48 * 128];
    const int m0 = blockIdx.x * 64;
    const int n0 = blockIdx.y * 128;
    const int tid = threadIdx.x;
    const int tm = tid >> 4;   // 16 -> 4 tokens
    const int tn = tid & 15;   // 16 -> 8 cols
    float acc[4][8] = {};
    for (int k0 = 0; k0 < 96; k0 += 48) {
        __syncthreads();
        for (int idx = tid; idx < 64 * 48; idx += 256) {
            int i = idx / 48, kk = idx - i * 48;
            sx[kk * 64 + i] = x[(m0 + i) * 96 + k0 + kk];
        }
        for (int idx = tid; idx < 48 * 128; idx += 256) {
            int kk = idx >> 7, nn = idx & 127;
            sw[kk * 128 + nn] = Wi[(k0 + kk) * 384 + n0 + nn];
        }
        __syncthreads();
#pragma unroll
        for (int kk = 0; kk < 48; kk++) {
            float4 a  = *(const float4*)&sx[kk * 64  + tm * 4];
            float4 b0 = *(const float4*)&sw[kk * 128 + tn * 8];
            float4 b1 = *(const float4*)&sw[kk * 128 + tn * 8 + 4];
            float av[4] = {a.x, a.y, a.z, a.w};
            float bv[8] = {b0.x, b0.y, b0.z, b0.w, b1.x, b1.y, b1.z, b1.w};
#pragma unroll
            for (int i = 0; i < 4; i++)
#pragma unroll
                for (int j = 0; j < 8; j++)
                    acc[i][j] = fmaf(av[i], bv[j], acc[i][j]);
        }
    }
#pragma unroll
    for (int i = 0; i < 4; i++) {
        int m = m0 + tm * 4 + i;
#pragma unroll
        for (int j = 0; j < 8; j++) {
            int n = n0 + tn * 8 + j;
            if (n < DI) g_xm[m * DI + n] = acc[i][j];
            else        g_z [m * DI + (n - DI)] = acc[i][j];
        }
    }
}

// ---------------- kernel 2: depthwise 3x3 conv + bias ----------------
__global__ void k_conv(const float* __restrict__ cw, const float* __restrict__ cb) {
    int idx = blockIdx.x * 256 + threadIdx.x;
    if (idx >= TOK * DI) return;
    int c = idx % DI, t = idx / DI;
    int b = t / LSEQ, r = t - b * LSEQ, h = r / WWW, w = r - h * WWW;
    float acc = cb[c];
#pragma unroll
    for (int dh = -1; dh <= 1; dh++) {
#pragma unroll
        for (int dw = -1; dw <= 1; dw++) {
            int hh = h + dh, ww = w + dw;
            if ((unsigned)hh < HH && (unsigned)ww < WWW)
                acc = fmaf(g_xm[(b * LSEQ + hh * WWW + ww) * DI + c],
                           cw[((dh + 1) * 3 + (dw + 1)) * DI + c], acc);
        }
    }
    g_xc[idx] = acc;
}

// ---------------- kernel 3: x-proj GEMM (6272 x 38 x 192) ----------------
#define XN 40
__global__ void __launch_bounds__(256) k_xproj(const float* __restrict__ Wx) {
    __shared__ float sx[48 * 64];
    __shared__ float sw[48 * XN];
    const int m0 = blockIdx.x * 64;
    const int tid = threadIdx.x;
    const int tn = tid & 7;    // 8 -> 5 cols
    const int tm = tid >> 3;   // 32 -> 2 tokens
    float acc[2][5] = {};
    for (int k0 = 0; k0 < 192; k0 += 48) {
        __syncthreads();
        for (int idx = tid; idx < 64 * 48; idx += 256) {
            int i = idx / 48, kk = idx - i * 48;
            sx[kk * 64 + i] = g_xc[(m0 + i) * DI + k0 + kk];
        }
        for (int idx = tid; idx < 48 * XN; idx += 256) {
            int kk = idx / XN, nn = idx - kk * XN;
            sw[idx] = (nn < 38) ? Wx[(k0 + kk) * 38 + nn] : 0.f;
        }
        __syncthreads();
#pragma unroll
        for (int kk = 0; kk < 48; kk++) {
            float2 a = *(const float2*)&sx[kk * 64 + tm * 2];
            float w[5];
#pragma unroll
            for (int j = 0; j < 5; j++) w[j] = sw[kk * XN + tn * 5 + j];
#pragma unroll
            for (int j = 0; j < 5; j++) {
                acc[0][j] = fmaf(a.x, w[j], acc[0][j]);
                acc[1][j] = fmaf(a.y, w[j], acc[1][j]);
            }
        }
    }
#pragma unroll
    for (int i = 0; i < 2; i++) {
        int m = m0 + tm * 2 + i;
#pragma unroll
        for (int j = 0; j < 5; j++) {
            int n = tn * 5 + j;
            float v = acc[i][j];
            if (n < RK)            g_dtr[m * RK + n] = v;
            else if (n < RK + NST) g_Bv[m * NST + n - RK] = v;
            else if (n < 38)       g_Cv[m * NST + n - RK - NST] = v;
        }
    }
}

// ---------------- kernel 4: dt-proj (rank 6) + softplus ----------------
__global__ void __launch_bounds__(256) k_dtproj(const float* __restrict__ Wd,
                                                const float* __restrict__ bd) {
    __shared__ float sd[16 * RK];
    __shared__ float swd[RK * DI];
    const int t0 = blockIdx.x * 16;
    const int tid = threadIdx.x;
    if (tid < 16 * RK) sd[tid] = g_dtr[t0 * RK + tid];
    for (int idx = tid; idx < RK * DI; idx += 256) swd[idx] = Wd[idx];
    __syncthreads();
#pragma unroll
    for (int p = 0; p < 12; p++) {
        int idx = p * 256 + tid;
        int t = idx / DI, c = idx - t * DI;
        float a = bd[c];
#pragma unroll
        for (int r = 0; r < RK; r++) a = fmaf(sd[t * RK + r], swd[r * DI + c], a);
        g_dt[(t0 + t) * DI + c] = (a > 20.f) ? a : log1pf(expf(a));
    }
}

// ---------------- kernel 5: scan pass 1 (chunk a_prod, h_end) ----------------
__global__ void __launch_bounds__(192) k_scan1(const float* __restrict__ A_log) {
    const int bx = blockIdx.x;         // g*56 + ch
    const int ch = bx % NCH, g = bx / NCH;
    const int d = g >> 1, b = g & 1;
    __shared__ float s_B[CLEN * NST];
    int t0, st; seq_base(d, b, ch, t0, st);
    const int c = threadIdx.x;
    for (int idx = c; idx < CLEN * NST; idx += 192) {
        int l = idx >> 4, n = idx & 15;
        s_B[idx] = g_Bv[(t0 + l * st) * NST + n];
    }
    float acl[16];
#pragma unroll
    for (int q = 0; q < 4; q++) {
        float4 v = ((const float4*)A_log)[c * 4 + q];
        acl[q*4+0] = -__expf(v.x) * 1.4426950408889634f;
        acl[q*4+1] = -__expf(v.y) * 1.4426950408889634f;
        acl[q*4+2] = -__expf(v.z) * 1.4426950408889634f;
        acl[q*4+3] = -__expf(v.w) * 1.4426950408889634f;
    }
    float h[16], ap[16];
#pragma unroll
    for (int n = 0; n < 16; n++) { h[n] = 0.f; ap[n] = 1.f; }
    __syncthreads();
    const float* pdt = g_dt + t0 * DI + c;
    const float* px  = g_xc + t0 * DI + c;
    const int stride = st * DI;
#pragma unroll 2
    for (int l = 0; l < CLEN; l++) {
        float dt = *pdt; float xv = *px;
        pdt += stride; px += stride;
        float dtx = dt * xv;
        float Bv[16];
#pragma unroll
        for (int q = 0; q < 4; q++) {
            float4 v = ((const float4*)(s_B + l * 16))[q];
            Bv[q*4+0] = v.x; Bv[q*4+1] = v.y; Bv[q*4+2] = v.z; Bv[q*4+3] = v.w;
        }
#pragma unroll
        for (int n = 0; n < 16; n++) {
            float a = ex2(dt * acl[n]);
            ap[n] *= a;
            h[n] = fmaf(a, h[n], dtx * Bv[n]);
        }
    }
    float4* pa = (float4*)&g_ap[(bx * DI + c) * NST];
    float4* ph = (float4*)&g_he[(bx * DI + c) * NST];
#pragma unroll
    for (int q = 0; q < 4; q++) {
        pa[q] = make_float4(ap[q*4], ap[q*4+1], ap[q*4+2], ap[q*4+3]);
        ph[q] = make_float4(h[q*4], h[q*4+1], h[q*4+2], h[q*4+3]);
    }
}

// ---------------- kernel 6: cross-chunk prefix combine ----------------
__global__ void k_combine() {
    int s = blockIdx.x * 256 + threadIdx.x;
    if (s >= GSEQ * DI * NST) return;
    int g = s / (DI * NST), sc = s - g * (DI * NST);
    float h = 0.f;
#pragma unroll 8
    for (int k = 0; k < NCH; k++) {
        int idx = (g * NCH + k) * (DI * NST) + sc;
        g_hs[idx] = h;
        h = fmaf(g_ap[idx], h, g_he[idx]);
    }
}

// ---------------- kernel 7: scan pass 2 (replay + emit y) ----------------
__global__ void __launch_bounds__(192) k_scan2(const float* __restrict__ A_log,
                                               const float* __restrict__ D_skip) {
    const int bx = blockIdx.x;
    const int ch = bx % NCH, g = bx / NCH;
    const int d = g >> 1, b = g & 1;
    __shared__ float s_B[CLEN * NST];
    __shared__ float s_C[CLEN * NST];
    int t0, st; seq_base(d, b, ch, t0, st);
    const int c = threadIdx.x;
    for (int idx = c; idx < CLEN * NST * 2; idx += 192) {
        int half = idx >= CLEN * NST;
        int r = idx - half * CLEN * NST;
        int l = r >> 4, n = r & 15;
        int t = t0 + l * st;
        if (half) s_C[r] = g_Cv[t * NST + n];
        else      s_B[r] = g_Bv[t * NST + n];
    }
    float acl[16];
#pragma unroll
    for (int q = 0; q < 4; q++) {
        float4 v = ((const float4*)A_log)[c * 4 + q];
        acl[q*4+0] = -__expf(v.x) * 1.4426950408889634f;
        acl[q*4+1] = -__expf(v.y) * 1.4426950408889634f;
        acl[q*4+2] = -__expf(v.z) * 1.4426950408889634f;
        acl[q*4+3] = -__expf(v.w) * 1.4426950408889634f;
    }
    float h[16];
    const float4* phs = (const float4*)&g_hs[(bx * DI + c) * NST];
#pragma unroll
    for (int q = 0; q < 4; q++) {
        float4 v = phs[q];
        h[q*4+0] = v.x; h[q*4+1] = v.y; h[q*4+2] = v.z; h[q*4+3] = v.w;
    }
    const float dsk = D_skip[c];
    __syncthreads();
    const float* pdt = g_dt + t0 * DI + c;
    const float* px  = g_xc + t0 * DI + c;
    const int stride = st * DI;
    float* py = g_ys + (g * LSEQ + ch * CLEN) * DI + c;
#pragma unroll 2
    for (int l = 0; l < CLEN; l++) {
        float dt = *pdt; float xv = *px;
        pdt += stride; px += stride;
        float dtx = dt * xv;
        float Bv[16], Cv[16];
#pragma unroll
        for (int q = 0; q < 4; q++) {
            float4 vb = ((const float4*)(s_B + l * 16))[q];
            float4 vc = ((const float4*)(s_C + l * 16))[q];
            Bv[q*4+0] = vb.x; Bv[q*4+1] = vb.y; Bv[q*4+2] = vb.z; Bv[q*4+3] = vb.w;
            Cv[q*4+0] = vc.x; Cv[q*4+1] = vc.y; Cv[q*4+2] = vc.z; Cv[q*4+3] = vc.w;
        }
        float y = 0.f;
#pragma unroll
        for (int n = 0; n < 16; n++) {
            float a = ex2(dt * acl[n]);
            h[n] = fmaf(a, h[n], dtx * Bv[n]);
            y = fmaf(h[n], Cv[n], y);
        }
        py[l * DI] = fmaf(dsk, xv, y);
    }
}

// ---------------- kernel 8: sum dirs, silu gate, out-proj ----------------
__global__ void __launch_bounds__(256) k_final(const float* __restrict__ Wo,
                                               float* __restrict__ out) {
    __shared__ float syT[192 * 36];   // [c][i], pad 36
    __shared__ float sw[48 * 96];
    const int t0 = blockIdx.x * 32;
    const int tid = threadIdx.x;
    for (int idx = tid; idx < 32 * 192; idx += 256) {
        int i = idx / 192, c = idx - i * 192;
        int t = t0 + i; int b = t / LSEQ; int l = t - b * LSEQ;
        float ys = 0.f;
#pragma unroll
        for (int dd = 0; dd < 4; dd++)
            ys += g_ys[((dd * 2 + b) * LSEQ + l) * DI + c];
        float z = g_z[t * DI + c];
        syT[c * 36 + i] = ys * (z / (1.f + __expf(-z)));
    }
    const int tm = tid >> 5;   // 8 -> 4 tokens
    const int tn = tid & 31;   // 32 -> 3 cols
    float acc[4][3] = {};
    for (int k0 = 0; k0 < 192; k0 += 48) {
        __syncthreads();
        for (int idx = tid; idx < 48 * 96; idx += 256) {
            int kk = idx / 96, nn = idx - kk * 96;
            sw[idx] = Wo[(k0 + kk) * 96 + nn];
        }
        __syncthreads();
#pragma unroll
        for (int kk = 0; kk < 48; kk++) {
            float4 a = *(const float4*)&syT[(k0 + kk) * 36 + tm * 4];
            float w0 = sw[kk * 96 + tn];
            float w1 = sw[kk * 96 + 32 + tn];
            float w2 = sw[kk * 96 + 64 + tn];
            float av[4] = {a.x, a.y, a.z, a.w};
#pragma unroll
            for (int i = 0; i < 4; i++) {
                acc[i][0] = fmaf(av[i], w0, acc[i][0]);
                acc[i][1] = fmaf(av[i], w1, acc[i][1]);
                acc[i][2] = fmaf(av[i], w2, acc[i][2]);
            }
        }
    }
#pragma unroll
    for (int i = 0; i < 4; i++) {
        int t = t0 + tm * 4 + i;
        out[t * DM + tn]      = acc[i][0];
        out[t * DM + 32 + tn] = acc[i][1];
        out[t * DM + 64 + tn] = acc[i][2];
    }
}

// ---------------- launcher ----------------
extern "C" void kernel_launch(void* const* d_in, const int* in_sizes, int n_in,
                              void* d_out, int out_size) {
    const float* x      = (const float*)d_in[0];
    const float* W_in   = (const float*)d_in[1];
    const float* conv_w = (const float*)d_in[2];
    const float* conv_b = (const float*)d_in[3];
    const float* W_xpr  = (const float*)d_in[4];
    const float* W_dt   = (const float*)d_in[5];
    const float* b_dt   = (const float*)d_in[6];
    const float* A_log  = (const float*)d_in[7];
    const float* D_skip = (const float*)d_in[8];
    const float* W_out  = (const float*)d_in[9];
    float* out = (float*)d_out;

    dim3 g1(TOK / 64, N2 / 128);
    k_inproj<<<g1, 256>>>(x, W_in);
    k_conv<<<(TOK * DI + 255) / 256, 256>>>(conv_w, conv_b);
    k_xproj<<<TOK / 64, 256>>>(W_xpr);
    k_dtproj<<<TOK / 16, 256>>>(W_dt, b_dt);
    k_scan1<<<GSEQ * NCH, 192>>>(A_log);
    k_combine<<<(GSEQ * DI * NST + 255) / 256, 256>>>();
    k_scan2<<<GSEQ * NCH, 192>>>(A_log, D_skip);
    k_final<<<TOK / 32, 256>>>(W_out, out);
}

// round 4
// speedup vs baseline: 1.5456x; 1.0637x over previous
#include <cuda_runtime.h>
#include <cuda_bf16.h>
#include <math.h>

// ---------------- problem constants ----------------
#define TOK    6272
#define LSEQ   3136
#define HH     56
#define WWW    56
#define DM     96
#define DI     192
#define N2     384
#define NST    16
#define RK     6
#define GSEQ   8
#define NCH    56
#define CLEN   56

// ---------------- scratch ----------------
__device__ float g_xm [TOK * DI];
__device__ float g_z  [TOK * DI];
__device__ float g_xc [TOK * DI];
__device__ float g_dt [TOK * DI];
__device__ float g_Bv [TOK * NST];
__device__ float g_Cv [TOK * NST];
__device__ float g_ap [GSEQ * NCH * DI * NST];
__device__ float g_he [GSEQ * NCH * DI * NST];
__device__ float g_hs [GSEQ * NCH * DI * NST];
__device__ float g_ys [GSEQ * LSEQ * DI];

typedef unsigned long long u64;
__device__ __forceinline__ float ex2(float x) {
    float r; asm("ex2.approx.f32 %0, %1;" : "=f"(r) : "f"(x)); return r;
}
__device__ __forceinline__ u64 pack2(float lo, float hi) {
    u64 r; asm("mov.b64 %0, {%1, %2};" : "=l"(r) : "f"(lo), "f"(hi)); return r;
}
__device__ __forceinline__ void unpack2(u64 v, float& lo, float& hi) {
    asm("mov.b64 {%0, %1}, %2;" : "=f"(lo), "=f"(hi) : "l"(v));
}
__device__ __forceinline__ u64 fma2(u64 a, u64 b, u64 c) {
    u64 d; asm("fma.rn.f32x2 %0, %1, %2, %3;" : "=l"(d) : "l"(a), "l"(b), "l"(c)); return d;
}
__device__ __forceinline__ u64 mul2(u64 a, u64 b) {
    u64 d; asm("mul.rn.f32x2 %0, %1, %2;" : "=l"(d) : "l"(a), "l"(b)); return d;
}

__device__ __forceinline__ void seq_base(int d, int b, int ch, int& t0, int& st) {
    if      (d == 0) { t0 = b * LSEQ + ch * WWW;      st = 1;   }
    else if (d == 1) { t0 = b * LSEQ + ch * WWW + 55; st = -1;  }
    else if (d == 2) { t0 = b * LSEQ + ch;            st = WWW; }
    else             { t0 = b * LSEQ + (55 - ch);     st = WWW; }
}

// ---------------- kernel 1: xz = x @ W_in -> xm / z ----------------
__global__ void __launch_bounds__(256) k_inproj(const float* __restrict__ x,
                                                const float* __restrict__ Wi) {
    __shared__ float sx[48 * 64];
    __shared__ float sw[48 * 128];
    const int m0 = blockIdx.x * 64;
    const int n0 = blockIdx.y * 128;
    const int tid = threadIdx.x;
    const int tm = tid >> 4;
    const int tn = tid & 15;
    float acc[4][8] = {};
    for (int k0 = 0; k0 < 96; k0 += 48) {
        __syncthreads();
        for (int idx = tid; idx < 64 * 48; idx += 256) {
            int i = idx / 48, kk = idx - i * 48;
            sx[kk * 64 + i] = x[(m0 + i) * 96 + k0 + kk];
        }
        for (int idx = tid; idx < 48 * 128; idx += 256) {
            int kk = idx >> 7, nn = idx & 127;
            sw[kk * 128 + nn] = Wi[(k0 + kk) * 384 + n0 + nn];
        }
        __syncthreads();
#pragma unroll
        for (int kk = 0; kk < 48; kk++) {
            float4 a  = *(const float4*)&sx[kk * 64  + tm * 4];
            float4 b0 = *(const float4*)&sw[kk * 128 + tn * 8];
            float4 b1 = *(const float4*)&sw[kk * 128 + tn * 8 + 4];
            float av[4] = {a.x, a.y, a.z, a.w};
            float bv[8] = {b0.x, b0.y, b0.z, b0.w, b1.x, b1.y, b1.z, b1.w};
#pragma unroll
            for (int i = 0; i < 4; i++)
#pragma unroll
                for (int j = 0; j < 8; j++)
                    acc[i][j] = fmaf(av[i], bv[j], acc[i][j]);
        }
    }
#pragma unroll
    for (int i = 0; i < 4; i++) {
        int m = m0 + tm * 4 + i;
#pragma unroll
        for (int j = 0; j < 8; j++) {
            int n = n0 + tn * 8 + j;
            if (n < DI) g_xm[m * DI + n] = acc[i][j];
            else        g_z [m * DI + (n - DI)] = acc[i][j];
        }
    }
}

// ---------------- kernel 2: fused conv3x3 + x-proj + dt-proj ----------------
#define SXP 193
#define XN  40
__global__ void __launch_bounds__(256) k_fuse(const float* __restrict__ cw,
                                              const float* __restrict__ cb,
                                              const float* __restrict__ Wx,
                                              const float* __restrict__ Wd,
                                              const float* __restrict__ bd) {
    __shared__ float sxc[32 * SXP];   // conv output [i][c], padded
    __shared__ float sw[48 * XN];
    __shared__ float swd[RK * DI];
    __shared__ float sbd[DI];
    __shared__ float sdtr[32 * 8];
    const int t0 = blockIdx.x * 32;
    const int tid = threadIdx.x;

    for (int idx = tid; idx < RK * DI; idx += 256) swd[idx] = Wd[idx];
    if (tid < DI) sbd[tid] = bd[tid];

    // conv phase
    for (int idx = tid; idx < 32 * DI; idx += 256) {
        int i = idx / DI, c = idx - i * DI;
        int t = t0 + i;
        int b = t / LSEQ, r = t - b * LSEQ, h = r / WWW, w = r - h * WWW;
        float acc = cb[c];
#pragma unroll
        for (int dh = -1; dh <= 1; dh++)
#pragma unroll
            for (int dw = -1; dw <= 1; dw++) {
                int hh = h + dh, ww = w + dw;
                if ((unsigned)hh < HH && (unsigned)ww < WWW)
                    acc = fmaf(g_xm[(b * LSEQ + hh * WWW + ww) * DI + c],
                               cw[((dh + 1) * 3 + (dw + 1)) * DI + c], acc);
            }
        sxc[i * SXP + c] = acc;
        g_xc[t * DI + c] = acc;
    }

    // x-proj GEMM: M=32, N=38(pad 40), K=192
    const int tm = tid >> 3;   // 32 rows
    const int tn = tid & 7;    // 8 -> 5 cols
    float acc[5] = {};
    for (int k0 = 0; k0 < 192; k0 += 48) {
        __syncthreads();
        for (int idx = tid; idx < 48 * XN; idx += 256) {
            int kk = idx / XN, nn = idx - kk * XN;
            sw[idx] = (nn < 38) ? Wx[(k0 + kk) * 38 + nn] : 0.f;
        }
        __syncthreads();
#pragma unroll
        for (int kk = 0; kk < 48; kk++) {
            float a = sxc[tm * SXP + k0 + kk];
            const float* wr = &sw[kk * XN + tn * 5];
#pragma unroll
            for (int j = 0; j < 5; j++) acc[j] = fmaf(a, wr[j], acc[j]);
        }
    }
#pragma unroll
    for (int j = 0; j < 5; j++) {
        int n = tn * 5 + j;
        if (n < RK)            sdtr[tm * 8 + n] = acc[j];
        else if (n < RK + NST) g_Bv[(t0 + tm) * NST + n - RK] = acc[j];
        else if (n < 38)       g_Cv[(t0 + tm) * NST + n - RK - NST] = acc[j];
    }
    __syncthreads();

    // dt-proj + softplus: 32 x 192
#pragma unroll
    for (int p = 0; p < 24; p++) {
        int idx = p * 256 + tid;
        int i = idx / DI, c = idx - i * DI;
        float a = sbd[c];
#pragma unroll
        for (int r = 0; r < RK; r++) a = fmaf(sdtr[i * 8 + r], swd[r * DI + c], a);
        g_dt[(t0 + i) * DI + c] = (a > 20.f) ? a : log1pf(expf(a));
    }
}

// ---------------- kernel 3: scan pass 1 ----------------
__global__ void __launch_bounds__(192) k_scan1(const float* __restrict__ A_log) {
    const int bx = blockIdx.x;
    const int ch = bx % NCH, g = bx / NCH;
    const int d = g >> 1, b = g & 1;
    __shared__ float s_B[CLEN * NST];
    int t0, st; seq_base(d, b, ch, t0, st);
    const int c = threadIdx.x;
    for (int idx = c; idx < CLEN * NST; idx += 192) {
        int l = idx >> 4, n = idx & 15;
        s_B[idx] = g_Bv[(t0 + l * st) * NST + n];
    }
    float acl[16];
#pragma unroll
    for (int q = 0; q < 4; q++) {
        float4 v = ((const float4*)A_log)[c * 4 + q];
        acl[q*4+0] = -__expf(v.x) * 1.4426950408889634f;
        acl[q*4+1] = -__expf(v.y) * 1.4426950408889634f;
        acl[q*4+2] = -__expf(v.z) * 1.4426950408889634f;
        acl[q*4+3] = -__expf(v.w) * 1.4426950408889634f;
    }
    u64 acl2[8], h2[8];
#pragma unroll
    for (int q = 0; q < 8; q++) { acl2[q] = pack2(acl[2*q], acl[2*q+1]); h2[q] = 0ull; }
    __syncthreads();
    const int stride = st * DI;
    const float* pdt = g_dt + t0 * DI + c;
    const float* px  = g_xc + t0 * DI + c;
    float dtc = *pdt, xc = *px;
    float S = 0.f;
#pragma unroll 2
    for (int l = 0; l < CLEN; l++) {
        float dt = dtc, xv = xc;
        if (l < CLEN - 1) { pdt += stride; px += stride; dtc = *pdt; xc = *px; }
        S += dt;
        float dtx = dt * xv;
        u64 dt2  = pack2(dt, dt);
        u64 dtx2 = pack2(dtx, dtx);
        const u64* b2 = (const u64*)(s_B + l * 16);
#pragma unroll
        for (int q = 0; q < 8; q++) {
            u64 arg = mul2(dt2, acl2[q]);
            float alo, ahi; unpack2(arg, alo, ahi);
            u64 a2 = pack2(ex2(alo), ex2(ahi));
            h2[q] = fma2(a2, h2[q], mul2(dtx2, b2[q]));
        }
    }
    const int base = (bx * DI + c) * NST;
    u64* pa = (u64*)&g_ap[base];
    u64* ph = (u64*)&g_he[base];
#pragma unroll
    for (int q = 0; q < 8; q++) {
        pa[q] = pack2(ex2(acl[2*q] * S), ex2(acl[2*q+1] * S));
        ph[q] = h2[q];
    }
}

// ---------------- kernel 4: cross-chunk prefix combine ----------------
__global__ void k_combine() {
    int s = blockIdx.x * 256 + threadIdx.x;
    if (s >= GSEQ * DI * NST) return;
    int g = s / (DI * NST), sc = s - g * (DI * NST);
    float h = 0.f;
#pragma unroll 8
    for (int k = 0; k < NCH; k++) {
        int idx = (g * NCH + k) * (DI * NST) + sc;
        g_hs[idx] = h;
        h = fmaf(g_ap[idx], h, g_he[idx]);
    }
}

// ---------------- kernel 5: scan pass 2 (replay + emit y) ----------------
__global__ void __launch_bounds__(192) k_scan2(const float* __restrict__ A_log,
                                               const float* __restrict__ D_skip) {
    const int bx = blockIdx.x;
    const int ch = bx % NCH, g = bx / NCH;
    const int d = g >> 1, b = g & 1;
    __shared__ float s_B[CLEN * NST];
    __shared__ float s_C[CLEN * NST];
    int t0, st; seq_base(d, b, ch, t0, st);
    const int c = threadIdx.x;
    for (int idx = c; idx < CLEN * NST * 2; idx += 192) {
        int half = idx >= CLEN * NST;
        int r = idx - half * CLEN * NST;
        int l = r >> 4, n = r & 15;
        int t = t0 + l * st;
        if (half) s_C[r] = g_Cv[t * NST + n];
        else      s_B[r] = g_Bv[t * NST + n];
    }
    float acl[16];
#pragma unroll
    for (int q = 0; q < 4; q++) {
        float4 v = ((const float4*)A_log)[c * 4 + q];
        acl[q*4+0] = -__expf(v.x) * 1.4426950408889634f;
        acl[q*4+1] = -__expf(v.y) * 1.4426950408889634f;
        acl[q*4+2] = -__expf(v.z) * 1.4426950408889634f;
        acl[q*4+3] = -__expf(v.w) * 1.4426950408889634f;
    }
    u64 acl2[8], h2[8];
    const int base = (bx * DI + c) * NST;
    const u64* phs = (const u64*)&g_hs[base];
#pragma unroll
    for (int q = 0; q < 8; q++) { acl2[q] = pack2(acl[2*q], acl[2*q+1]); h2[q] = phs[q]; }
    const float dsk = D_skip[c];
    __syncthreads();
    const int stride = st * DI;
    const float* pdt = g_dt + t0 * DI + c;
    const float* px  = g_xc + t0 * DI + c;
    float dtc = *pdt, xc = *px;
    float* py = g_ys + (g * LSEQ + ch * CLEN) * DI + c;
#pragma unroll 2
    for (int l = 0; l < CLEN; l++) {
        float dt = dtc, xv = xc;
        if (l < CLEN - 1) { pdt += stride; px += stride; dtc = *pdt; xc = *px; }
        float dtx = dt * xv;
        u64 dt2  = pack2(dt, dt);
        u64 dtx2 = pack2(dtx, dtx);
        const u64* b2 = (const u64*)(s_B + l * 16);
        const u64* c2 = (const u64*)(s_C + l * 16);
        u64 y2 = 0ull;
#pragma unroll
        for (int q = 0; q < 8; q++) {
            u64 arg = mul2(dt2, acl2[q]);
            float alo, ahi; unpack2(arg, alo, ahi);
            u64 a2 = pack2(ex2(alo), ex2(ahi));
            h2[q] = fma2(a2, h2[q], mul2(dtx2, b2[q]));
            y2 = fma2(h2[q], c2[q], y2);
        }
        float ylo, yhi; unpack2(y2, ylo, yhi);
        py[l * DI] = fmaf(dsk, xv, ylo + yhi);
    }
}

// ---------------- kernel 6: sum dirs, silu gate, out-proj ----------------
__global__ void __launch_bounds__(256) k_final(const float* __restrict__ Wo,
                                               float* __restrict__ out) {
    __shared__ float syT[192 * 36];
    __shared__ float sw[48 * 96];
    const int t0 = blockIdx.x * 32;
    const int tid = threadIdx.x;
    for (int idx = tid; idx < 32 * 192; idx += 256) {
        int i = idx / 192, c = idx - i * 192;
        int t = t0 + i; int b = t / LSEQ; int l = t - b * LSEQ;
        float ys = 0.f;
#pragma unroll
        for (int dd = 0; dd < 4; dd++)
            ys += g_ys[((dd * 2 + b) * LSEQ + l) * DI + c];
        float z = g_z[t * DI + c];
        syT[c * 36 + i] = ys * (z / (1.f + __expf(-z)));
    }
    const int tm = tid >> 5;
    const int tn = tid & 31;
    float acc[4][3] = {};
    for (int k0 = 0; k0 < 192; k0 += 48) {
        __syncthreads();
        for (int idx = tid; idx < 48 * 96; idx += 256) {
            int kk = idx / 96, nn = idx - kk * 96;
            sw[idx] = Wo[(k0 + kk) * 96 + nn];
        }
        __syncthreads();
#pragma unroll
        for (int kk = 0; kk < 48; kk++) {
            float4 a = *(const float4*)&syT[(k0 + kk) * 36 + tm * 4];
            float w0 = sw[kk * 96 + tn];
            float w1 = sw[kk * 96 + 32 + tn];
            float w2 = sw[kk * 96 + 64 + tn];
            float av[4] = {a.x, a.y, a.z, a.w};
#pragma unroll
            for (int i = 0; i < 4; i++) {
                acc[i][0] = fmaf(av[i], w0, acc[i][0]);
                acc[i][1] = fmaf(av[i], w1, acc[i][1]);
                acc[i][2] = fmaf(av[i], w2, acc[i][2]);
            }
        }
    }
#pragma unroll
    for (int i = 0; i < 4; i++) {
        int t = t0 + tm * 4 + i;
        out[t * DM + tn]      = acc[i][0];
        out[t * DM + 32 + tn] = acc[i][1];
        out[t * DM + 64 + tn] = acc[i][2];
    }
}

// ---------------- launcher ----------------
extern "C" void kernel_launch(void* const* d_in, const int* in_sizes, int n_in,
                              void* d_out, int out_size) {
    const float* x      = (const float*)d_in[0];
    const float* W_in   = (const float*)d_in[1];
    const float* conv_w = (const float*)d_in[2];
    const float* conv_b = (const float*)d_in[3];
    const float* W_xpr  = (const float*)d_in[4];
    const float* W_dt   = (const float*)d_in[5];
    const float* b_dt   = (const float*)d_in[6];
    const float* A_log  = (const float*)d_in[7];
    const float* D_skip = (const float*)d_in[8];
    const float* W_out  = (const float*)d_in[9];
    float* out = (float*)d_out;

    dim3 g1(TOK / 64, N2 / 128);
    k_inproj<<<g1, 256>>>(x, W_in);
    k_fuse<<<TOK / 32, 256>>>(conv_w, conv_b, W_xpr, W_dt, b_dt);
    k_scan1<<<GSEQ * NCH, 192>>>(A_log);
    k_combine<<<(GSEQ * DI * NST + 255) / 256, 256>>>();
    k_scan2<<<GSEQ * NCH, 192>>>(A_log, D_skip);
    k_final<<<TOK / 32, 256>>>(W_out, out);
}

// round 7
// speedup vs baseline: 1.7707x; 1.1457x over previous
#include <cuda_runtime.h>
#include <cuda_bf16.h>
#include <math.h>

// ---------------- problem constants ----------------
#define TOK    6272
#define LSEQ   3136
#define HH     56
#define WWW    56
#define DM     96
#define DI     192
#define N2     384
#define NST    16
#define RK     6
#define GSEQ   8
#define NCH    56
#define CLEN   56
#define SEG    (DI * NST)   // 3072 states per (g,chunk)

// ---------------- scratch ----------------
__device__ float  g_xm [TOK * DI];
__device__ float  g_z  [TOK * DI];
__device__ __align__(16) float2 g_dtx[TOK * DI];           // (dt, x_conv)
__device__ float  g_Bv [TOK * NST];
__device__ float  g_Cv [TOK * NST];
__device__ __align__(16) float2 g_ab [GSEQ * NCH * SEG];   // (a_prod, h_end)
__device__ __align__(16) float  g_hs [GSEQ * NCH * SEG];   // h_start
__device__ float  g_ys [GSEQ * LSEQ * DI];

typedef unsigned long long u64;
__device__ __forceinline__ float ex2(float x) {
    float r; asm("ex2.approx.f32 %0, %1;" : "=f"(r) : "f"(x)); return r;
}
__device__ __forceinline__ u64 pack2(float lo, float hi) {
    u64 r; asm("mov.b64 %0, {%1, %2};" : "=l"(r) : "f"(lo), "f"(hi)); return r;
}
__device__ __forceinline__ void unpack2(u64 v, float& lo, float& hi) {
    asm("mov.b64 {%0, %1}, %2;" : "=f"(lo), "=f"(hi) : "l"(v));
}
__device__ __forceinline__ u64 fma2(u64 a, u64 b, u64 c) {
    u64 d; asm("fma.rn.f32x2 %0, %1, %2, %3;" : "=l"(d) : "l"(a), "l"(b), "l"(c)); return d;
}
__device__ __forceinline__ u64 mul2(u64 a, u64 b) {
    u64 d; asm("mul.rn.f32x2 %0, %1, %2;" : "=l"(d) : "l"(a), "l"(b)); return d;
}

__device__ __forceinline__ void seq_base(int d, int b, int ch, int& t0, int& st) {
    if      (d == 0) { t0 = b * LSEQ + ch * WWW;      st = 1;   }
    else if (d == 1) { t0 = b * LSEQ + ch * WWW + 55; st = -1;  }
    else if (d == 2) { t0 = b * LSEQ + ch;            st = WWW; }
    else             { t0 = b * LSEQ + (55 - ch);     st = WWW; }
}

// ---------------- kernel 1: xz = x @ W_in -> xm / z ----------------
__global__ void __launch_bounds__(256) k_inproj(const float* __restrict__ x,
                                                const float* __restrict__ Wi) {
    __shared__ float sx[48 * 64];
    __shared__ float sw[48 * 128];
    const int m0 = blockIdx.x * 64;
    const int n0 = blockIdx.y * 128;
    const int tid = threadIdx.x;
    const int tm = tid >> 4;
    const int tn = tid & 15;
    float acc[4][8] = {};
    for (int k0 = 0; k0 < 96; k0 += 48) {
        __syncthreads();
        for (int idx = tid; idx < 64 * 48; idx += 256) {
            int i = idx / 48, kk = idx - i * 48;
            sx[kk * 64 + i] = x[(m0 + i) * 96 + k0 + kk];
        }
        for (int idx = tid; idx < 48 * 128; idx += 256) {
            int kk = idx >> 7, nn = idx & 127;
            sw[kk * 128 + nn] = Wi[(k0 + kk) * 384 + n0 + nn];
        }
        __syncthreads();
#pragma unroll
        for (int kk = 0; kk < 48; kk++) {
            float4 a  = *(const float4*)&sx[kk * 64  + tm * 4];
            float4 b0 = *(const float4*)&sw[kk * 128 + tn * 8];
            float4 b1 = *(const float4*)&sw[kk * 128 + tn * 8 + 4];
            float av[4] = {a.x, a.y, a.z, a.w};
            float bv[8] = {b0.x, b0.y, b0.z, b0.w, b1.x, b1.y, b1.z, b1.w};
#pragma unroll
            for (int i = 0; i < 4; i++)
#pragma unroll
                for (int j = 0; j < 8; j++)
                    acc[i][j] = fmaf(av[i], bv[j], acc[i][j]);
        }
    }
#pragma unroll
    for (int i = 0; i < 4; i++) {
        int m = m0 + tm * 4 + i;
#pragma unroll
        for (int j = 0; j < 8; j++) {
            int n = n0 + tn * 8 + j;
            if (n < DI) g_xm[m * DI + n] = acc[i][j];
            else        g_z [m * DI + (n - DI)] = acc[i][j];
        }
    }
}

// ---------------- kernel 2: fused conv3x3 + x-proj + dt-proj ----------------
#define SXP 193
#define XN  40
__global__ void __launch_bounds__(256) k_fuse(const float* __restrict__ cw,
                                              const float* __restrict__ cb,
                                              const float* __restrict__ Wx,
                                              const float* __restrict__ Wd,
                                              const float* __restrict__ bd) {
    __shared__ float sxc[32 * SXP];
    __shared__ float sw[48 * XN];
    __shared__ float swd[RK * DI];
    __shared__ float sbd[DI];
    __shared__ float sdtr[32 * 8];
    __shared__ float scw[9 * DI];
    __shared__ float scb[DI];
    const int t0 = blockIdx.x * 32;
    const int tid = threadIdx.x;

    for (int idx = tid; idx < RK * DI; idx += 256) swd[idx] = Wd[idx];
    for (int idx = tid; idx < 9 * DI; idx += 256) scw[idx] = cw[idx];
    if (tid < DI) { sbd[tid] = bd[tid]; scb[tid] = cb[tid]; }
    __syncthreads();

    // conv phase
    for (int idx = tid; idx < 32 * DI; idx += 256) {
        int i = idx / DI, c = idx - i * DI;
        int t = t0 + i;
        int b = t / LSEQ, r = t - b * LSEQ, h = r / WWW, w = r - h * WWW;
        float acc = scb[c];
#pragma unroll
        for (int dh = -1; dh <= 1; dh++)
#pragma unroll
            for (int dw = -1; dw <= 1; dw++) {
                int hh = h + dh, ww = w + dw;
                if ((unsigned)hh < HH && (unsigned)ww < WWW)
                    acc = fmaf(g_xm[(b * LSEQ + hh * WWW + ww) * DI + c],
                               scw[((dh + 1) * 3 + (dw + 1)) * DI + c], acc);
            }
        sxc[i * SXP + c] = acc;
    }

    // x-proj GEMM: M=32, N=38(pad 40), K=192
    const int tm = tid >> 3;
    const int tn = tid & 7;
    float acc[5] = {};
    for (int k0 = 0; k0 < 192; k0 += 48) {
        __syncthreads();
        for (int idx = tid; idx < 48 * XN; idx += 256) {
            int kk = idx / XN, nn = idx - kk * XN;
            sw[idx] = (nn < 38) ? Wx[(k0 + kk) * 38 + nn] : 0.f;
        }
        __syncthreads();
#pragma unroll
        for (int kk = 0; kk < 48; kk++) {
            float a = sxc[tm * SXP + k0 + kk];
            const float* wr = &sw[kk * XN + tn * 5];
#pragma unroll
            for (int j = 0; j < 5; j++) acc[j] = fmaf(a, wr[j], acc[j]);
        }
    }
#pragma unroll
    for (int j = 0; j < 5; j++) {
        int n = tn * 5 + j;
        if (n < RK)            sdtr[tm * 8 + n] = acc[j];
        else if (n < RK + NST) g_Bv[(t0 + tm) * NST + n - RK] = acc[j];
        else if (n < 38)       g_Cv[(t0 + tm) * NST + n - RK - NST] = acc[j];
    }
    __syncthreads();

    // dt-proj + softplus, pack with conv output
#pragma unroll
    for (int p = 0; p < 24; p++) {
        int idx = p * 256 + tid;
        int i = idx / DI, c = idx - i * DI;
        float a = sbd[c];
#pragma unroll
        for (int r = 0; r < RK; r++) a = fmaf(sdtr[i * 8 + r], swd[r * DI + c], a);
        float dt = (a > 20.f) ? a : log1pf(expf(a));
        g_dtx[(t0 + i) * DI + c] = make_float2(dt, sxc[i * SXP + c]);
    }
}

// ---------------- kernel 3: scan pass 1 ----------------
__global__ void __launch_bounds__(192) k_scan1(const float* __restrict__ A_log) {
    const int bx = blockIdx.x;
    const int ch = bx % NCH, g = bx / NCH;
    const int d = g >> 1, b = g & 1;
    __shared__ __align__(16) float s_B[CLEN * NST];
    int t0, st; seq_base(d, b, ch, t0, st);
    const int c = threadIdx.x;
    for (int idx = c; idx < CLEN * NST; idx += 192) {
        int l = idx >> 4, n = idx & 15;
        s_B[idx] = g_Bv[(t0 + l * st) * NST + n];
    }
    float acl[16];
#pragma unroll
    for (int q = 0; q < 4; q++) {
        float4 v = ((const float4*)A_log)[c * 4 + q];
        acl[q*4+0] = -__expf(v.x) * 1.4426950408889634f;
        acl[q*4+1] = -__expf(v.y) * 1.4426950408889634f;
        acl[q*4+2] = -__expf(v.z) * 1.4426950408889634f;
        acl[q*4+3] = -__expf(v.w) * 1.4426950408889634f;
    }
    u64 acl2[8], h2[8];
#pragma unroll
    for (int q = 0; q < 8; q++) { acl2[q] = pack2(acl[2*q], acl[2*q+1]); h2[q] = 0ull; }
    __syncthreads();
    const int stride = st * DI;
    const float2* pdx = g_dtx + t0 * DI + c;
    float2 cur = *pdx;
    float S = 0.f;
#pragma unroll 2
    for (int l = 0; l < CLEN; l++) {
        float dt = cur.x, xv = cur.y;
        if (l < CLEN - 1) { pdx += stride; cur = *pdx; }
        S += dt;
        float dtx = dt * xv;
        u64 dt2  = pack2(dt, dt);
        u64 dtx2 = pack2(dtx, dtx);
        const u64* b2 = (const u64*)(s_B + l * 16);
#pragma unroll
        for (int q = 0; q < 8; q++) {
            u64 arg = mul2(dt2, acl2[q]);
            float alo, ahi; unpack2(arg, alo, ahi);
            u64 a2 = pack2(ex2(alo), ex2(ahi));
            h2[q] = fma2(a2, h2[q], mul2(dtx2, b2[q]));
        }
    }
    float4* pw = (float4*)&g_ab[(bx * DI + c) * NST];
#pragma unroll
    for (int q = 0; q < 8; q++) {
        float h0, h1; unpack2(h2[q], h0, h1);
        pw[q] = make_float4(ex2(acl[2*q] * S), h0, ex2(acl[2*q+1] * S), h1);
    }
}

// ---------------- kernel 4: cross-chunk prefix combine ----------------
__global__ void __launch_bounds__(128) k_combine() {
    const int s = blockIdx.x * 128 + threadIdx.x;   // 24576
    const int g = s / SEG, sc = s - g * SEG;
    const float2* pab = g_ab + g * NCH * SEG + sc;
    float* phs = g_hs + g * NCH * SEG + sc;
    float h = 0.f;
#pragma unroll
    for (int half = 0; half < 2; half++) {
        float2 v[28];
#pragma unroll
        for (int j = 0; j < 28; j++) v[j] = pab[(half * 28 + j) * SEG];
#pragma unroll
        for (int j = 0; j < 28; j++) {
            phs[(half * 28 + j) * SEG] = h;
            h = fmaf(v[j].x, h, v[j].y);
        }
    }
}

// ---------------- kernel 5: scan pass 2 (replay + emit y) ----------------
__global__ void __launch_bounds__(192) k_scan2(const float* __restrict__ A_log,
                                               const float* __restrict__ D_skip) {
    const int bx = blockIdx.x;
    const int ch = bx % NCH, g = bx / NCH;
    const int d = g >> 1, b = g & 1;
    __shared__ __align__(16) float s_B[CLEN * NST];
    __shared__ __align__(16) float s_C[CLEN * NST];
    int t0, st; seq_base(d, b, ch, t0, st);
    const int c = threadIdx.x;
    for (int idx = c; idx < CLEN * NST * 2; idx += 192) {
        int half = idx >= CLEN * NST;
        int r = idx - half * CLEN * NST;
        int l = r >> 4, n = r & 15;
        int t = t0 + l * st;
        if (half) s_C[r] = g_Cv[t * NST + n];
        else      s_B[r] = g_Bv[t * NST + n];
    }
    float acl[16];
#pragma unroll
    for (int q = 0; q < 4; q++) {
        float4 v = ((const float4*)A_log)[c * 4 + q];
        acl[q*4+0] = -__expf(v.x) * 1.4426950408889634f;
        acl[q*4+1] = -__expf(v.y) * 1.4426950408889634f;
        acl[q*4+2] = -__expf(v.z) * 1.4426950408889634f;
        acl[q*4+3] = -__expf(v.w) * 1.4426950408889634f;
    }
    u64 acl2[8], h2[8];
    const int base = (bx * DI + c) * NST;
    const u64* phs = (const u64*)&g_hs[base];
#pragma unroll
    for (int q = 0; q < 8; q++) { acl2[q] = pack2(acl[2*q], acl[2*q+1]); h2[q] = phs[q]; }
    const float dsk = D_skip[c];
    __syncthreads();
    const int stride = st * DI;
    const float2* pdx = g_dtx + t0 * DI + c;
    float2 cur = *pdx;
    float* py = g_ys + (g * LSEQ + ch * CLEN) * DI + c;
#pragma unroll 2
    for (int l = 0; l < CLEN; l++) {
        float dt = cur.x, xv = cur.y;
        if (l < CLEN - 1) { pdx += stride; cur = *pdx; }
        float dtx = dt * xv;
        u64 dt2  = pack2(dt, dt);
        u64 dtx2 = pack2(dtx, dtx);
        const u64* b2 = (const u64*)(s_B + l * 16);
        const u64* c2 = (const u64*)(s_C + l * 16);
        u64 y2 = 0ull;
#pragma unroll
        for (int q = 0; q < 8; q++) {
            u64 arg = mul2(dt2, acl2[q]);
            float alo, ahi; unpack2(arg, alo, ahi);
            u64 a2 = pack2(ex2(alo), ex2(ahi));
            h2[q] = fma2(a2, h2[q], mul2(dtx2, b2[q]));
            y2 = fma2(h2[q], c2[q], y2);
        }
        float ylo, yhi; unpack2(y2, ylo, yhi);
        py[l * DI] = fmaf(dsk, xv, ylo + yhi);
    }
}

// ---------------- kernel 6: sum dirs, silu gate, out-proj ----------------
__global__ void __launch_bounds__(256) k_final(const float* __restrict__ Wo,
                                               float* __restrict__ out) {
    __shared__ float syT[192 * 36];
    __shared__ float sw[48 * 96];
    const int t0 = blockIdx.x * 32;
    const int tid = threadIdx.x;
    for (int idx = tid; idx < 32 * 192; idx += 256) {
        int i = idx / 192, c = idx - i * 192;
        int t = t0 + i; int b = t / LSEQ; int l = t - b * LSEQ;
        float ys = 0.f;
#pragma unroll
        for (int dd = 0; dd < 4; dd++)
            ys += g_ys[((dd * 2 + b) * LSEQ + l) * DI + c];
        float z = g_z[t * DI + c];
        syT[c * 36 + i] = ys * (z / (1.f + __expf(-z)));
    }
    const int tm = tid >> 5;
    const int tn = tid & 31;
    float acc[4][3] = {};
    for (int k0 = 0; k0 < 192; k0 += 48) {
        __syncthreads();
        for (int idx = tid; idx < 48 * 96; idx += 256) {
            int kk = idx / 96, nn = idx - kk * 96;
            sw[idx] = Wo[(k0 + kk) * 96 + nn];
        }
        __syncthreads();
#pragma unroll
        for (int kk = 0; kk < 48; kk++) {
            float4 a = *(const float4*)&syT[(k0 + kk) * 36 + tm * 4];
            float w0 = sw[kk * 96 + tn];
            float w1 = sw[kk * 96 + 32 + tn];
            float w2 = sw[kk * 96 + 64 + tn];
            float av[4] = {a.x, a.y, a.z, a.w};
#pragma unroll
            for (int i = 0; i < 4; i++) {
                acc[i][0] = fmaf(av[i], w0, acc[i][0]);
                acc[i][1] = fmaf(av[i], w1, acc[i][1]);
                acc[i][2] = fmaf(av[i], w2, acc[i][2]);
            }
        }
    }
#pragma unroll
    for (int i = 0; i < 4; i++) {
        int t = t0 + tm * 4 + i;
        out[t * DM + tn]      = acc[i][0];
        out[t * DM + 32 + tn] = acc[i][1];
        out[t * DM + 64 + tn] = acc[i][2];
    }
}

// ---------------- launcher ----------------
extern "C" void kernel_launch(void* const* d_in, const int* in_sizes, int n_in,
                              void* d_out, int out_size) {
    const float* x      = (const float*)d_in[0];
    const float* W_in   = (const float*)d_in[1];
    const float* conv_w = (const float*)d_in[2];
    const float* conv_b = (const float*)d_in[3];
    const float* W_xpr  = (const float*)d_in[4];
    const float* W_dt   = (const float*)d_in[5];
    const float* b_dt   = (const float*)d_in[6];
    const float* A_log  = (const float*)d_in[7];
    const float* D_skip = (const float*)d_in[8];
    const float* W_out  = (const float*)d_in[9];
    float* out = (float*)d_out;

    dim3 g1(TOK / 64, N2 / 128);
    k_inproj<<<g1, 256>>>(x, W_in);
    k_fuse<<<TOK / 32, 256>>>(conv_w, conv_b, W_xpr, W_dt, b_dt);
    k_scan1<<<GSEQ * NCH, 192>>>(A_log);
    k_combine<<<GSEQ * SEG / 128, 128>>>();
    k_scan2<<<GSEQ * NCH, 192>>>(A_log, D_skip);
    k_final<<<TOK / 32, 256>>>(W_out, out);
}